// round 6
// baseline (speedup 1.0000x reference)
#include <cuda_runtime.h>
#include <cuda_fp16.h>
#include <math.h>

#define TT 1024
#define NENV 8192
#define CHUNKS 64
#define STEPS 16            // TT / CHUNKS
#define MTOT (TT * NENV)    // 8388608
#define VEC 4
#define BLK 128
#define GX (NENV / (VEC * BLK))   // 16 blocks along env dim

#define GAMMA_F 0.99f
#define GLF (0.99f * 0.95f)

// ---------------- scratch (device globals) -----------------------------------
__device__ unsigned g_bu[MTOT];              // packed half2: (b, u) per element
__device__ unsigned g_abits[CHUNKS * NENV];  // per-step a!=0 bit
__device__ float    g_Ag[CHUNKS * NENV];     // chunk aggregate A
__device__ float    g_Bg[CHUNKS * NENV];     // chunk aggregate B
__device__ float    g_SA [CHUNKS * NENV];    // Σ A_t   (within chunk)
__device__ float    g_SB [CHUNKS * NENV];    // Σ B_t
__device__ float    g_SA2[CHUNKS * NENV];    // Σ A_t^2
__device__ float    g_SAB[CHUNKS * NENV];    // Σ A_t B_t
__device__ float    g_SB2[CHUNKS * NENV];    // Σ B_t^2
__device__ float    g_gin[CHUNKS * NENV];    // incoming gae per chunk
__device__ double   g_acc[5];                // 0:Σg 1:Σg² 2:vloss 3:ent 4:action
__device__ float    g_stats[2];              // mean, inv_std
__device__ unsigned g_tick1, g_tick2;

// ---------------- block reduce (BLK = 128 threads = 4 warps) ------------------
__device__ __forceinline__ float block_reduce(float v, float* smem) {
    #pragma unroll
    for (int o = 16; o > 0; o >>= 1) v += __shfl_down_sync(0xffffffffu, v, o);
    int lane = threadIdx.x & 31, w = threadIdx.x >> 5;
    if (lane == 0) smem[w] = v;
    __syncthreads();
    if (w == 0) {
        v = (lane < 4) ? smem[lane] : 0.0f;
        v += __shfl_down_sync(0xffffffffu, v, 2);
        v += __shfl_down_sync(0xffffffffu, v, 1);
    }
    return v; // valid on thread 0
}

// ---------------- K0: reset accumulators + tickets ----------------------------
__global__ void k_init() {
    int i = threadIdx.x;
    if (i < 5) g_acc[i] = 0.0;
    if (i == 5) g_tick1 = 0u;
    if (i == 6) g_tick2 = 0u;
}

// ---------------- K1: coeff pass (vec4 envs) ----------------------------------
__global__ void __launch_bounds__(BLK) k_coeff(
    const float* __restrict__ rew, const float* __restrict__ masks,
    const float* __restrict__ bad, const float* __restrict__ vp,
    const float* __restrict__ lastv, const float* __restrict__ nval)
{
    const int n0 = (blockIdx.x * BLK + threadIdx.x) * VEC;
    const int c  = blockIdx.y;
    const int lo = c * STEPS, hi = lo + STEPS;

    float4 vn4 = (hi == TT) ? *(const float4*)(lastv + n0)
                            : *(const float4*)(vp + hi * NENV + n0);
    float vn[VEC] = {vn4.x, vn4.y, vn4.z, vn4.w};
    float A[VEC], B[VEC], SA[VEC], SB[VEC], SA2[VEC], SAB[VEC], SB2[VEC];
    unsigned bits[VEC];
    #pragma unroll
    for (int j = 0; j < VEC; ++j) {
        A[j] = 1.0f; B[j] = 0.0f;
        SA[j] = SB[j] = SA2[j] = SAB[j] = SB2[j] = 0.0f;
        bits[j] = 0u;
    }

    #pragma unroll 8
    for (int t = hi - 1; t >= lo; --t) {
        const int idx = t * NENV + n0;
        float4 v4  = *(const float4*)(vp + idx);
        float4 m4  = *(const float4*)(masks + idx + NENV);
        float4 bd4 = *(const float4*)(bad + idx + NENV);
        float4 r4  = *(const float4*)(rew + idx);
        float4 nv4 = *(const float4*)(nval + idx);
        const float v[VEC]  = {v4.x, v4.y, v4.z, v4.w};
        const float m[VEC]  = {m4.x, m4.y, m4.z, m4.w};
        const float bd[VEC] = {bd4.x, bd4.y, bd4.z, bd4.w};
        const float r[VEC]  = {r4.x, r4.y, r4.z, r4.w};
        const float nv[VEC] = {nv4.x, nv4.y, nv4.z, nv4.w};
        unsigned sw[VEC];
        #pragma unroll
        for (int j = 0; j < VEC; ++j) {
            float delta = r[j] + GAMMA_F * vn[j] * m[j] - v[j];
            float b = delta * bd[j];
            float u = nv[j] - v[j];
            __half2 h = __floats2half2_rn(b, u);
            sw[j] = *reinterpret_cast<unsigned*>(&h);
            float br = __half2float(__low2half(h));   // fp16-rounded b (consistent!)
            float anz = m[j] * bd[j];                  // 0 or 1
            bits[j] |= (anz != 0.0f ? 1u : 0u) << (t - lo);
            float a = anz * GLF;
            B[j] = a * B[j] + br;
            A[j] = a * A[j];
            SA[j]  += A[j];          SB[j]  += B[j];
            SA2[j] += A[j] * A[j];   SAB[j] += A[j] * B[j];  SB2[j] += B[j] * B[j];
            vn[j] = v[j];
        }
        *(uint4*)(g_bu + idx) = make_uint4(sw[0], sw[1], sw[2], sw[3]);
    }

    const int ci = c * NENV + n0;
    *(uint4*) (g_abits + ci) = make_uint4(bits[0], bits[1], bits[2], bits[3]);
    *(float4*)(g_Ag  + ci) = make_float4(A[0], A[1], A[2], A[3]);
    *(float4*)(g_Bg  + ci) = make_float4(B[0], B[1], B[2], B[3]);
    *(float4*)(g_SA  + ci) = make_float4(SA[0], SA[1], SA[2], SA[3]);
    *(float4*)(g_SB  + ci) = make_float4(SB[0], SB[1], SB[2], SB[3]);
    *(float4*)(g_SA2 + ci) = make_float4(SA2[0], SA2[1], SA2[2], SA2[3]);
    *(float4*)(g_SAB + ci) = make_float4(SAB[0], SAB[1], SAB[2], SAB[3]);
    *(float4*)(g_SB2 + ci) = make_float4(SB2[0], SB2[1], SB2[2], SB2[3]);
}

// ---------------- K2: chunk scan + exact Σg, Σg² + stats ----------------------
__global__ void __launch_bounds__(BLK) k_scan() {
    __shared__ float sm0[4], sm1[4];
    const int n0 = (blockIdx.x * BLK + threadIdx.x) * VEC;

    float g[VEC] = {0.f, 0.f, 0.f, 0.f};
    float sg = 0.f, sg2 = 0.f;
    #pragma unroll 8
    for (int c = CHUNKS - 1; c >= 0; --c) {
        const int ci = c * NENV + n0;
        float4 Ag  = *(const float4*)(g_Ag  + ci);
        float4 Bg  = *(const float4*)(g_Bg  + ci);
        float4 SA  = *(const float4*)(g_SA  + ci);
        float4 SB  = *(const float4*)(g_SB  + ci);
        float4 SA2 = *(const float4*)(g_SA2 + ci);
        float4 SAB = *(const float4*)(g_SAB + ci);
        float4 SB2 = *(const float4*)(g_SB2 + ci);
        *(float4*)(g_gin + ci) = make_float4(g[0], g[1], g[2], g[3]);
        const float a_[VEC]  = {Ag.x, Ag.y, Ag.z, Ag.w};
        const float b_[VEC]  = {Bg.x, Bg.y, Bg.z, Bg.w};
        const float sa[VEC]  = {SA.x, SA.y, SA.z, SA.w};
        const float sb[VEC]  = {SB.x, SB.y, SB.z, SB.w};
        const float sa2[VEC] = {SA2.x, SA2.y, SA2.z, SA2.w};
        const float sab[VEC] = {SAB.x, SAB.y, SAB.z, SAB.w};
        const float sb2[VEC] = {SB2.x, SB2.y, SB2.z, SB2.w};
        #pragma unroll
        for (int j = 0; j < VEC; ++j) {
            sg  += sa[j] * g[j] + sb[j];
            sg2 += (sa2[j] * g[j] + 2.0f * sab[j]) * g[j] + sb2[j];
            g[j] = a_[j] * g[j] + b_[j];
        }
    }

    float rs  = block_reduce(sg,  sm0);
    float rs2 = block_reduce(sg2, sm1);
    if (threadIdx.x == 0) {
        atomicAdd(&g_acc[0], (double)rs);
        atomicAdd(&g_acc[1], (double)rs2);
        __threadfence();
        unsigned t = atomicAdd(&g_tick1, 1u);
        if (t == gridDim.x - 1) {
            volatile double* acc = g_acc;
            double S = acc[0], S2 = acc[1];
            double M = (double)MTOT;
            double mean = S / M;
            double var = (S2 - S * S / M) / (M - 1.0);
            g_stats[0] = (float)mean;
            g_stats[1] = (float)(1.0 / (sqrt(var) + 1e-5));
        }
    }
}

// ---------------- K3: fused main pass (vec4; reads bu, lp, plp, ent only) -----
__global__ void __launch_bounds__(BLK) k_main(
    const float* __restrict__ ent, const float* __restrict__ lp,
    const float* __restrict__ plp, float* __restrict__ out)
{
    __shared__ float sm0[4], sm1[4], sm2[4];
    const int n0 = (blockIdx.x * BLK + threadIdx.x) * VEC;
    const int c  = blockIdx.y;
    const int lo = c * STEPS, hi = lo + STEPS;
    const int ci = c * NENV + n0;

    const float mean = g_stats[0], istd = g_stats[1];
    float4 gin4 = *(const float4*)(g_gin + ci);
    uint4  bt4  = *(const uint4*) (g_abits + ci);
    float g[VEC] = {gin4.x, gin4.y, gin4.z, gin4.w};
    const unsigned bits[VEC] = {bt4.x, bt4.y, bt4.z, bt4.w};

    float vl = 0.f, es = 0.f, act = 0.f;
    #pragma unroll 8
    for (int t = hi - 1; t >= lo; --t) {
        const int idx = t * NENV + n0;
        uint4  bu4 = *(const uint4*)(g_bu + idx);
        float4 lp4 = *(const float4*)(lp + idx);
        float4 pp4 = *(const float4*)(plp + idx);
        float4 en4 = *(const float4*)(ent + idx);
        const unsigned buw[VEC] = {bu4.x, bu4.y, bu4.z, bu4.w};
        const float lpv[VEC] = {lp4.x, lp4.y, lp4.z, lp4.w};
        const float ppv[VEC] = {pp4.x, pp4.y, pp4.z, pp4.w};
        const float env[VEC] = {en4.x, en4.y, en4.z, en4.w};
        const int s = t - lo;
        #pragma unroll
        for (int j = 0; j < VEC; ++j) {
            __half2 h = *reinterpret_cast<const __half2*>(&buw[j]);
            float2 bu = __half22float2(h);
            float am = ((bits[j] >> s) & 1u) ? GLF : 0.0f;
            g[j] = fmaf(am, g[j], bu.x);

            // action loss
            float a = (g[j] - mean) * istd;
            float r = __expf(lpv[j] - ppv[j]);
            float rc = fminf(fmaxf(r, 0.8f), 1.2f);
            act += fminf(r * a, rc * a);

            // value loss: d1 = u - g, d2 = clamp(u) - g
            float u  = bu.y;
            float d1 = u - g[j];
            float d2 = fminf(fmaxf(u, -0.2f), 0.2f) - g[j];
            vl += fmaxf(d1 * d1, d2 * d2);

            es += env[j];
        }
    }

    float rvl = block_reduce(vl,  sm0);
    float res = block_reduce(es,  sm1);
    float rac = block_reduce(act, sm2);
    if (threadIdx.x == 0) {
        atomicAdd(&g_acc[2], (double)rvl);
        atomicAdd(&g_acc[3], (double)res);
        atomicAdd(&g_acc[4], (double)rac);
        __threadfence();
        unsigned tk = atomicAdd(&g_tick2, 1u);
        if (tk == gridDim.x * gridDim.y - 1) {
            volatile double* acc = g_acc;
            double M = (double)MTOT;
            double value_term = 0.25 * (acc[2] / M);   // 0.5*mean * VALUE_LOSS_COEF
            double action_loss = -(acc[4] / M);
            double ent_mean = acc[3] / M;
            out[0] = (float)(value_term + action_loss - 0.01 * ent_mean);
        }
    }
}

// ---------------- launch ------------------------------------------------------
extern "C" void kernel_launch(void* const* d_in, const int* in_sizes, int n_in,
                              void* d_out, int out_size)
{
    const float* rew   = (const float*)d_in[0];
    const float* masks = (const float*)d_in[1];
    const float* bad   = (const float*)d_in[2];
    const float* vp    = (const float*)d_in[3];
    const float* lastv = (const float*)d_in[4];
    const float* lp    = (const float*)d_in[5];
    const float* plp   = (const float*)d_in[6];
    const float* nval  = (const float*)d_in[7];
    const float* ent   = (const float*)d_in[8];
    float* out = (float*)d_out;

    k_init<<<1, 32>>>();

    dim3 grid(GX, CHUNKS);
    k_coeff<<<grid, BLK>>>(rew, masks, bad, vp, lastv, nval);
    k_scan<<<GX, BLK>>>();
    k_main<<<grid, BLK>>>(ent, lp, plp, out);
}

// round 7
// speedup vs baseline: 1.1158x; 1.1158x over previous
#include <cuda_runtime.h>
#include <cuda_fp16.h>
#include <math.h>

#define TT 1024
#define NENV 8192
#define CHUNKS 64
#define STEPS 16            // TT / CHUNKS
#define MTOT (TT * NENV)    // 8388608
#define VEC 2
#define BLK 128
#define GX (NENV / (VEC * BLK))   // 32 blocks along env dim

#define GAMMA_F 0.99f
#define GLF (0.99f * 0.95f)

// ---------------- scratch (device globals; zero-initialized) ------------------
__device__ unsigned g_bu[MTOT];              // packed half2: (b, u) per element
__device__ unsigned g_abits[CHUNKS * NENV];  // per-step a!=0 bit
__device__ float    g_Ag[CHUNKS * NENV];     // chunk aggregate A
__device__ float    g_Bg[CHUNKS * NENV];     // chunk aggregate B
__device__ float    g_SA [CHUNKS * NENV];    // Σ A_t   (within chunk)
__device__ float    g_SB [CHUNKS * NENV];    // Σ B_t
__device__ float    g_SA2[CHUNKS * NENV];    // Σ A_t^2
__device__ float    g_SAB[CHUNKS * NENV];    // Σ A_t B_t
__device__ float    g_SB2[CHUNKS * NENV];    // Σ B_t^2
__device__ float    g_gin[CHUNKS * NENV];    // incoming gae per chunk
__device__ double   g_acc[5];                // 0:Σg 1:Σg² 2:vloss 3:ent 4:action
__device__ float    g_stats[2];              // mean, inv_std
__device__ unsigned g_tick1, g_tick2;        // self-resetting tickets

// ---------------- block reduce (BLK = 128 threads = 4 warps) ------------------
__device__ __forceinline__ float block_reduce(float v, float* smem) {
    #pragma unroll
    for (int o = 16; o > 0; o >>= 1) v += __shfl_down_sync(0xffffffffu, v, o);
    int lane = threadIdx.x & 31, w = threadIdx.x >> 5;
    if (lane == 0) smem[w] = v;
    __syncthreads();
    if (w == 0) {
        v = (lane < 4) ? smem[lane] : 0.0f;
        v += __shfl_down_sync(0xffffffffu, v, 2);
        v += __shfl_down_sync(0xffffffffu, v, 1);
    }
    return v; // valid on thread 0
}

// ---------------- K1: coeff pass (vec2 envs, capped unroll) -------------------
__global__ void __launch_bounds__(BLK) k_coeff(
    const float* __restrict__ rew, const float* __restrict__ masks,
    const float* __restrict__ bad, const float* __restrict__ vp,
    const float* __restrict__ lastv, const float* __restrict__ nval)
{
    const int n0 = (blockIdx.x * BLK + threadIdx.x) * VEC;
    const int c  = blockIdx.y;
    const int lo = c * STEPS, hi = lo + STEPS;

    float2 vn2 = (hi == TT) ? *(const float2*)(lastv + n0)
                            : *(const float2*)(vp + hi * NENV + n0);
    float vn[VEC] = {vn2.x, vn2.y};
    float A[VEC], B[VEC], SA[VEC], SB[VEC], SA2[VEC], SAB[VEC], SB2[VEC];
    unsigned bits[VEC];
    #pragma unroll
    for (int j = 0; j < VEC; ++j) {
        A[j] = 1.0f; B[j] = 0.0f;
        SA[j] = SB[j] = SA2[j] = SAB[j] = SB2[j] = 0.0f;
        bits[j] = 0u;
    }

    #pragma unroll 4
    for (int t = hi - 1; t >= lo; --t) {
        const int idx = t * NENV + n0;
        float2 v2  = *(const float2*)(vp + idx);
        float2 m2  = *(const float2*)(masks + idx + NENV);
        float2 bd2 = *(const float2*)(bad + idx + NENV);
        float2 r2  = *(const float2*)(rew + idx);
        float2 nv2 = *(const float2*)(nval + idx);
        const float v[VEC]  = {v2.x, v2.y};
        const float m[VEC]  = {m2.x, m2.y};
        const float bd[VEC] = {bd2.x, bd2.y};
        const float r[VEC]  = {r2.x, r2.y};
        const float nv[VEC] = {nv2.x, nv2.y};
        unsigned sw[VEC];
        #pragma unroll
        for (int j = 0; j < VEC; ++j) {
            float delta = r[j] + GAMMA_F * vn[j] * m[j] - v[j];
            float b = delta * bd[j];
            float u = nv[j] - v[j];
            __half2 h = __floats2half2_rn(b, u);
            sw[j] = *reinterpret_cast<unsigned*>(&h);
            float br = __half2float(__low2half(h));   // fp16-rounded b (consistent!)
            float anz = m[j] * bd[j];                  // 0 or 1
            bits[j] |= (anz != 0.0f ? 1u : 0u) << (t - lo);
            float a = anz * GLF;
            B[j] = a * B[j] + br;
            A[j] = a * A[j];
            SA[j]  += A[j];          SB[j]  += B[j];
            SA2[j] += A[j] * A[j];   SAB[j] += A[j] * B[j];  SB2[j] += B[j] * B[j];
            vn[j] = v[j];
        }
        *(uint2*)(g_bu + idx) = make_uint2(sw[0], sw[1]);
    }

    const int ci = c * NENV + n0;
    *(uint2*) (g_abits + ci) = make_uint2(bits[0], bits[1]);
    *(float2*)(g_Ag  + ci) = make_float2(A[0], A[1]);
    *(float2*)(g_Bg  + ci) = make_float2(B[0], B[1]);
    *(float2*)(g_SA  + ci) = make_float2(SA[0], SA[1]);
    *(float2*)(g_SB  + ci) = make_float2(SB[0], SB[1]);
    *(float2*)(g_SA2 + ci) = make_float2(SA2[0], SA2[1]);
    *(float2*)(g_SAB + ci) = make_float2(SAB[0], SAB[1]);
    *(float2*)(g_SB2 + ci) = make_float2(SB2[0], SB2[1]);
}

// ---------------- K2: chunk scan + exact Σg, Σg² + stats ----------------------
__global__ void __launch_bounds__(BLK) k_scan() {
    __shared__ float sm0[4], sm1[4];
    const int n0 = (blockIdx.x * BLK + threadIdx.x) * VEC;

    float g[VEC] = {0.f, 0.f};
    float sg = 0.f, sg2 = 0.f;
    #pragma unroll 4
    for (int c = CHUNKS - 1; c >= 0; --c) {
        const int ci = c * NENV + n0;
        float2 Ag  = *(const float2*)(g_Ag  + ci);
        float2 Bg  = *(const float2*)(g_Bg  + ci);
        float2 SA  = *(const float2*)(g_SA  + ci);
        float2 SB  = *(const float2*)(g_SB  + ci);
        float2 SA2 = *(const float2*)(g_SA2 + ci);
        float2 SAB = *(const float2*)(g_SAB + ci);
        float2 SB2 = *(const float2*)(g_SB2 + ci);
        *(float2*)(g_gin + ci) = make_float2(g[0], g[1]);
        const float a_[VEC]  = {Ag.x, Ag.y};
        const float b_[VEC]  = {Bg.x, Bg.y};
        const float sa[VEC]  = {SA.x, SA.y};
        const float sb[VEC]  = {SB.x, SB.y};
        const float sa2[VEC] = {SA2.x, SA2.y};
        const float sab[VEC] = {SAB.x, SAB.y};
        const float sb2[VEC] = {SB2.x, SB2.y};
        #pragma unroll
        for (int j = 0; j < VEC; ++j) {
            sg  += sa[j] * g[j] + sb[j];
            sg2 += (sa2[j] * g[j] + 2.0f * sab[j]) * g[j] + sb2[j];
            g[j] = a_[j] * g[j] + b_[j];
        }
    }

    float rs  = block_reduce(sg,  sm0);
    float rs2 = block_reduce(sg2, sm1);
    if (threadIdx.x == 0) {
        atomicAdd(&g_acc[0], (double)rs);
        atomicAdd(&g_acc[1], (double)rs2);
        __threadfence();
        unsigned t = atomicAdd(&g_tick1, 1u);
        if (t == gridDim.x - 1) {
            volatile double* acc = g_acc;
            double S = acc[0], S2 = acc[1];
            double M = (double)MTOT;
            double mean = S / M;
            double var = (S2 - S * S / M) / (M - 1.0);
            g_stats[0] = (float)mean;
            g_stats[1] = (float)(1.0 / (sqrt(var) + 1e-5));
            // self-reset for next graph replay
            g_acc[0] = 0.0; g_acc[1] = 0.0;
            g_tick1 = 0u;
        }
    }
}

// ---------------- K3: fused main pass (vec2) ----------------------------------
__global__ void __launch_bounds__(BLK) k_main(
    const float* __restrict__ ent, const float* __restrict__ lp,
    const float* __restrict__ plp, float* __restrict__ out)
{
    __shared__ float sm0[4], sm1[4], sm2[4];
    const int n0 = (blockIdx.x * BLK + threadIdx.x) * VEC;
    const int c  = blockIdx.y;
    const int lo = c * STEPS, hi = lo + STEPS;
    const int ci = c * NENV + n0;

    const float mean = g_stats[0], istd = g_stats[1];
    float2 gin2 = *(const float2*)(g_gin + ci);
    uint2  bt2  = *(const uint2*) (g_abits + ci);
    float g[VEC] = {gin2.x, gin2.y};
    const unsigned bits[VEC] = {bt2.x, bt2.y};

    float vl = 0.f, es = 0.f, act = 0.f;
    #pragma unroll 8
    for (int t = hi - 1; t >= lo; --t) {
        const int idx = t * NENV + n0;
        uint2  bu2 = *(const uint2*)(g_bu + idx);
        float2 lp2 = *(const float2*)(lp + idx);
        float2 pp2 = *(const float2*)(plp + idx);
        float2 en2 = *(const float2*)(ent + idx);
        const unsigned buw[VEC] = {bu2.x, bu2.y};
        const float lpv[VEC] = {lp2.x, lp2.y};
        const float ppv[VEC] = {pp2.x, pp2.y};
        const float env[VEC] = {en2.x, en2.y};
        const int s = t - lo;
        #pragma unroll
        for (int j = 0; j < VEC; ++j) {
            __half2 h = *reinterpret_cast<const __half2*>(&buw[j]);
            float2 bu = __half22float2(h);
            float am = ((bits[j] >> s) & 1u) ? GLF : 0.0f;
            g[j] = fmaf(am, g[j], bu.x);

            // action loss
            float a = (g[j] - mean) * istd;
            float r = __expf(lpv[j] - ppv[j]);
            float rc = fminf(fmaxf(r, 0.8f), 1.2f);
            act += fminf(r * a, rc * a);

            // value loss: d1 = u - g, d2 = clamp(u) - g
            float u  = bu.y;
            float d1 = u - g[j];
            float d2 = fminf(fmaxf(u, -0.2f), 0.2f) - g[j];
            vl += fmaxf(d1 * d1, d2 * d2);

            es += env[j];
        }
    }

    float rvl = block_reduce(vl,  sm0);
    float res = block_reduce(es,  sm1);
    float rac = block_reduce(act, sm2);
    if (threadIdx.x == 0) {
        atomicAdd(&g_acc[2], (double)rvl);
        atomicAdd(&g_acc[3], (double)res);
        atomicAdd(&g_acc[4], (double)rac);
        __threadfence();
        unsigned tk = atomicAdd(&g_tick2, 1u);
        if (tk == gridDim.x * gridDim.y - 1) {
            volatile double* acc = g_acc;
            double M = (double)MTOT;
            double value_term = 0.25 * (acc[2] / M);   // 0.5*mean * VALUE_LOSS_COEF
            double action_loss = -(acc[4] / M);
            double ent_mean = acc[3] / M;
            out[0] = (float)(value_term + action_loss - 0.01 * ent_mean);
            // self-reset for next graph replay
            g_acc[2] = 0.0; g_acc[3] = 0.0; g_acc[4] = 0.0;
            g_tick2 = 0u;
        }
    }
}

// ---------------- launch ------------------------------------------------------
extern "C" void kernel_launch(void* const* d_in, const int* in_sizes, int n_in,
                              void* d_out, int out_size)
{
    const float* rew   = (const float*)d_in[0];
    const float* masks = (const float*)d_in[1];
    const float* bad   = (const float*)d_in[2];
    const float* vp    = (const float*)d_in[3];
    const float* lastv = (const float*)d_in[4];
    const float* lp    = (const float*)d_in[5];
    const float* plp   = (const float*)d_in[6];
    const float* nval  = (const float*)d_in[7];
    const float* ent   = (const float*)d_in[8];
    float* out = (float*)d_out;

    dim3 grid(GX, CHUNKS);
    k_coeff<<<grid, BLK>>>(rew, masks, bad, vp, lastv, nval);
    k_scan<<<GX, BLK>>>();
    k_main<<<grid, BLK>>>(ent, lp, plp, out);
}

// round 8
// speedup vs baseline: 1.4345x; 1.2856x over previous
#include <cuda_runtime.h>
#include <cuda_fp16.h>
#include <math.h>

#define TT 1024
#define NENV 8192
#define CHUNKS 32
#define STEPS 32            // TT / CHUNKS
#define MTOT (TT * NENV)    // 8388608
#define BLK 256
#define GX (NENV / BLK)     // 32 blocks along env dim

#define GAMMA_F 0.99f
#define GLF (0.99f * 0.95f)

// ---------------- scratch (device globals; zero-initialized) ------------------
__device__ unsigned g_bu[MTOT];              // packed half2: (b, u) per element
__device__ unsigned g_abits[CHUNKS * NENV];  // per-step a!=0 bit, 32 steps/word
__device__ float    g_Ag[CHUNKS * NENV];     // chunk aggregate A
__device__ float    g_Bg[CHUNKS * NENV];     // chunk aggregate B
__device__ float    g_SA [CHUNKS * NENV];    // Σ A_t   (within chunk)
__device__ float    g_SB [CHUNKS * NENV];    // Σ B_t
__device__ float    g_SA2[CHUNKS * NENV];    // Σ A_t^2
__device__ float    g_SAB[CHUNKS * NENV];    // Σ A_t B_t
__device__ float    g_SB2[CHUNKS * NENV];    // Σ B_t^2
__device__ float    g_gin[CHUNKS * NENV];    // incoming gae per chunk
__device__ double   g_acc[5];                // 0:Σg 1:Σg² 2:vloss 3:ent 4:action
__device__ float    g_stats[2];              // mean, inv_std
__device__ unsigned g_tick1, g_tick2;        // self-resetting tickets

// ---------------- block reduce (256 threads = 8 warps) ------------------------
__device__ __forceinline__ float block_reduce(float v, float* smem) {
    #pragma unroll
    for (int o = 16; o > 0; o >>= 1) v += __shfl_down_sync(0xffffffffu, v, o);
    int lane = threadIdx.x & 31, w = threadIdx.x >> 5;
    if (lane == 0) smem[w] = v;
    __syncthreads();
    if (w == 0) {
        v = (lane < 8) ? smem[lane] : 0.0f;
        #pragma unroll
        for (int o = 4; o > 0; o >>= 1) v += __shfl_down_sync(0xffffffffu, v, o);
    }
    return v; // valid on thread 0
}

// ---------------- K1: coeff pass — packed (b,u), a-bits, aggregates, moments --
__global__ void __launch_bounds__(BLK) k_coeff(
    const float* __restrict__ rew, const float* __restrict__ masks,
    const float* __restrict__ bad, const float* __restrict__ vp,
    const float* __restrict__ lastv, const float* __restrict__ nval)
{
    const int n  = blockIdx.x * BLK + threadIdx.x;
    const int c  = blockIdx.y;
    const int lo = c * STEPS, hi = lo + STEPS;

    float v_next = (hi == TT) ? lastv[n] : vp[hi * NENV + n];
    float A = 1.0f, B = 0.0f;
    float SA = 0.f, SB = 0.f, SA2 = 0.f, SAB = 0.f, SB2 = 0.f;
    unsigned bits = 0u;

    #pragma unroll 8
    for (int t = hi - 1; t >= lo; --t) {
        int idx = t * NENV + n;
        float v  = vp[idx];
        float m  = masks[idx + NENV];
        float bd = bad[idx + NENV];
        float r  = rew[idx];
        float nv = nval[idx];
        float delta = r + GAMMA_F * v_next * m - v;
        float b = delta * bd;
        float u = nv - v;
        __half2 h = __floats2half2_rn(b, u);
        g_bu[idx] = *reinterpret_cast<unsigned*>(&h);
        float br = __half2float(__low2half(h));  // fp16-rounded b (consistent!)
        float anz = m * bd;                       // exactly 0 or 1
        bits |= (anz != 0.0f ? 1u : 0u) << (t - lo);
        float a = anz * GLF;
        B = a * B + br;                           // (A,B) = f_t ∘ (A,B)
        A = a * A;
        SA += A;  SB += B;
        SA2 += A * A;  SAB += A * B;  SB2 += B * B;
        v_next = v;
    }
    int ci = c * NENV + n;
    g_abits[ci] = bits;
    g_Ag[ci] = A;   g_Bg[ci] = B;
    g_SA[ci] = SA;  g_SB[ci] = SB;
    g_SA2[ci] = SA2; g_SAB[ci] = SAB; g_SB2[ci] = SB2;
}

// ---------------- K2: chunk scan + exact Σg, Σg² + stats ----------------------
__global__ void __launch_bounds__(BLK) k_scan() {
    __shared__ float sm0[8], sm1[8];
    const int n = blockIdx.x * BLK + threadIdx.x;

    float g = 0.0f, sg = 0.0f, sg2 = 0.0f;
    #pragma unroll
    for (int c = CHUNKS - 1; c >= 0; --c) {
        int i = c * NENV + n;
        g_gin[i] = g;
        sg  += g_SA[i] * g + g_SB[i];
        sg2 += (g_SA2[i] * g + 2.0f * g_SAB[i]) * g + g_SB2[i];
        g = g_Ag[i] * g + g_Bg[i];
    }

    float rs  = block_reduce(sg,  sm0);
    float rs2 = block_reduce(sg2, sm1);
    if (threadIdx.x == 0) {
        atomicAdd(&g_acc[0], (double)rs);
        atomicAdd(&g_acc[1], (double)rs2);
        __threadfence();
        unsigned t = atomicAdd(&g_tick1, 1u);
        if (t == gridDim.x - 1) {
            volatile double* acc = g_acc;
            double S = acc[0], S2 = acc[1];
            double M = (double)MTOT;
            double mean = S / M;
            double var = (S2 - S * S / M) / (M - 1.0);
            g_stats[0] = (float)mean;
            g_stats[1] = (float)(1.0 / (sqrt(var) + 1e-5));
            // self-reset for next graph replay
            g_acc[0] = 0.0; g_acc[1] = 0.0;
            g_tick1 = 0u;
        }
    }
}

// ---------------- K3: fused main pass (reads bu, lp, plp, ent only) -----------
__global__ void __launch_bounds__(BLK) k_main(
    const float* __restrict__ ent, const float* __restrict__ lp,
    const float* __restrict__ plp, float* __restrict__ out)
{
    __shared__ float sm0[8], sm1[8], sm2[8];
    const int n  = blockIdx.x * BLK + threadIdx.x;
    const int c  = blockIdx.y;
    const int lo = c * STEPS, hi = lo + STEPS;
    const int ci = c * NENV + n;

    const float mean = g_stats[0], istd = g_stats[1];
    float g = g_gin[ci];
    const unsigned bits = g_abits[ci];

    float vl = 0.f, es = 0.f, act = 0.f;
    #pragma unroll 8
    for (int t = hi - 1; t >= lo; --t) {
        const int idx = t * NENV + n;
        unsigned buw = g_bu[idx];
        __half2 h = *reinterpret_cast<const __half2*>(&buw);
        float2 bu = __half22float2(h);
        float am = ((bits >> (t - lo)) & 1u) ? GLF : 0.0f;
        g = fmaf(am, g, bu.x);                    // gae recurrence

        // action loss
        float a = (g - mean) * istd;
        float r = __expf(lp[idx] - plp[idx]);
        float rc = fminf(fmaxf(r, 0.8f), 1.2f);
        act += fminf(r * a, rc * a);

        // value loss: d1 = u - g, d2 = clamp(u) - g
        float u  = bu.y;
        float d1 = u - g;
        float d2 = fminf(fmaxf(u, -0.2f), 0.2f) - g;
        vl += fmaxf(d1 * d1, d2 * d2);

        es += ent[idx];
    }

    float rvl = block_reduce(vl,  sm0);
    float res = block_reduce(es,  sm1);
    float rac = block_reduce(act, sm2);
    if (threadIdx.x == 0) {
        atomicAdd(&g_acc[2], (double)rvl);
        atomicAdd(&g_acc[3], (double)res);
        atomicAdd(&g_acc[4], (double)rac);
        __threadfence();
        unsigned tk = atomicAdd(&g_tick2, 1u);
        if (tk == gridDim.x * gridDim.y - 1) {
            volatile double* acc = g_acc;
            double M = (double)MTOT;
            double value_term = 0.25 * (acc[2] / M);   // 0.5*mean * VALUE_LOSS_COEF
            double action_loss = -(acc[4] / M);
            double ent_mean = acc[3] / M;
            out[0] = (float)(value_term + action_loss - 0.01 * ent_mean);
            // self-reset for next graph replay
            g_acc[2] = 0.0; g_acc[3] = 0.0; g_acc[4] = 0.0;
            g_tick2 = 0u;
        }
    }
}

// ---------------- launch ------------------------------------------------------
extern "C" void kernel_launch(void* const* d_in, const int* in_sizes, int n_in,
                              void* d_out, int out_size)
{
    const float* rew   = (const float*)d_in[0];
    const float* masks = (const float*)d_in[1];
    const float* bad   = (const float*)d_in[2];
    const float* vp    = (const float*)d_in[3];
    const float* lastv = (const float*)d_in[4];
    const float* lp    = (const float*)d_in[5];
    const float* plp   = (const float*)d_in[6];
    const float* nval  = (const float*)d_in[7];
    const float* ent   = (const float*)d_in[8];
    float* out = (float*)d_out;

    dim3 grid(GX, CHUNKS);
    k_coeff<<<grid, BLK>>>(rew, masks, bad, vp, lastv, nval);
    k_scan<<<GX, BLK>>>();
    k_main<<<grid, BLK>>>(ent, lp, plp, out);
}